// round 2
// baseline (speedup 1.0000x reference)
#include <cuda_runtime.h>
#include <cuda_bf16.h>
#include <cstdint>
#include <math.h>

// Problem constants
#define T_TOKENS 16384
#define HID      2880
#define NE       128
#define TOPK     4

// Tiling
#define MT       64      // tokens per block
#define KB       16      // K-tile
#define THREADS  256

// Packed f32x2 helpers (sm_103a): ptxas never auto-fuses these from C++.
#define FMA_F32X2(d, a, b, c) \
    asm("fma.rn.f32x2 %0, %1, %2, %3;" : "=l"(d) : "l"(a), "l"(b), "l"(c))
#define PACK_DUP_F32X2(out, f) do {                                    \
    unsigned int _ai = __float_as_uint(f);                             \
    asm("mov.b64 %0, {%1, %2};" : "=l"(out) : "r"(_ai), "r"(_ai));     \
} while (0)

// Pre-transposed weight: g_Wt[k][e] = W[e][k]   (1.47 MB static scratch)
__device__ float g_Wt[HID * NE];

union F2U { unsigned long long u; float2 f; };

__global__ void transpose_w_kernel(const float* __restrict__ W) {
    int idx = blockIdx.x * blockDim.x + threadIdx.x;
    if (idx < HID * NE) {
        int k = idx >> 7;       // / 128
        int e = idx & (NE - 1);
        g_Wt[idx] = W[e * HID + k];
    }
}

__global__ __launch_bounds__(THREADS)
void router_kernel(const float* __restrict__ X,
                   const int*   __restrict__ mask,
                   const float* __restrict__ bias,
                   const float* __restrict__ vbias,
                   float* __restrict__ out,
                   int write_idx)
{
    __shared__ float As[KB][MT];          // 4 KB   (transposed A tile)
    __shared__ float Bs[KB][NE];          // 8 KB   (transposed W tile)
    __shared__ float Lg[MT][NE + 1];      // 33 KB  (logits, pad 129 -> conflict-free column scan)
    __shared__ int   s_top_i[MT][TOPK];
    __shared__ float s_top_p[MT][TOPK];

    const int tid  = threadIdx.x;
    const int eg   = tid & 15;            // expert group: experts eg*8 .. eg*8+7
    const int tg   = tid >> 4;            // token group:  tokens  tg*4 .. tg*4+3
    const int row0 = blockIdx.x * MT;

    // 4 tokens x 8 experts = 16 packed f32x2 accumulators (pairs along expert dim)
    unsigned long long acc[4][4];
#pragma unroll
    for (int i = 0; i < 4; i++)
#pragma unroll
        for (int j = 0; j < 4; j++) acc[i][j] = 0ULL;

    // --- gmem load mapping ---
    // A tile: 256 float4 (one/thread): thread -> (token = tid>>2, chunk = tid&3)
    const int at = tid >> 2;
    const int ac = tid & 3;
    // B tile: 512 float4 (two/thread): r-th load -> row kk = r*8 + (tid>>5), col4 = tid&31
    const int bk = tid >> 5;
    const int be = tid & 31;

    const float* Xrow = X + (size_t)(row0 + at) * HID + ac * 4;

    // software pipeline: preload tile 0
    float4 a_pre  = *(const float4*)(Xrow);
    float4 b_pre0 = *(const float4*)(g_Wt + (size_t)(bk)     * NE + be * 4);
    float4 b_pre1 = *(const float4*)(g_Wt + (size_t)(bk + 8) * NE + be * 4);

    for (int kt = 0; kt < HID; kt += KB) {
        __syncthreads();
        // store tiles (A transposed: 4 scalar STS; B: conflict-free float4 STS)
#pragma unroll
        for (int j = 0; j < 4; j++)
            As[ac * 4 + j][at] = ((const float*)&a_pre)[j];
        *(float4*)&Bs[bk][be * 4]     = b_pre0;
        *(float4*)&Bs[bk + 8][be * 4] = b_pre1;
        __syncthreads();

        // prefetch next tile while computing this one
        if (kt + KB < HID) {
            a_pre  = *(const float4*)(Xrow + kt + KB);
            b_pre0 = *(const float4*)(g_Wt + (size_t)(kt + KB + bk)     * NE + be * 4);
            b_pre1 = *(const float4*)(g_Wt + (size_t)(kt + KB + bk + 8) * NE + be * 4);
        }

#pragma unroll
        for (int kk = 0; kk < KB; kk++) {
            // a: broadcast float4 (4 tokens), b: two float4 = 4 f32x2 pairs, no repack
            const float4     a  = *(const float4*)&As[kk][tg * 4];
            const ulonglong2 bA = *(const ulonglong2*)&Bs[kk][eg * 8];
            const ulonglong2 bB = *(const ulonglong2*)&Bs[kk][eg * 8 + 4];
            unsigned long long bp0 = bA.x, bp1 = bA.y, bp2 = bB.x, bp3 = bB.y;
            const float av4[4] = {a.x, a.y, a.z, a.w};
#pragma unroll
            for (int i = 0; i < 4; i++) {
                unsigned long long ad;
                PACK_DUP_F32X2(ad, av4[i]);
                FMA_F32X2(acc[i][0], ad, bp0, acc[i][0]);
                FMA_F32X2(acc[i][1], ad, bp1, acc[i][1]);
                FMA_F32X2(acc[i][2], ad, bp2, acc[i][2]);
                FMA_F32X2(acc[i][3], ad, bp3, acc[i][3]);
            }
        }
    }

    // --- epilogue: add bias (+ vision bias for vision tokens), stage logits in smem ---
    int mmask[4];
#pragma unroll
    for (int i = 0; i < 4; i++) mmask[i] = mask[row0 + tg * 4 + i];

#pragma unroll
    for (int j = 0; j < 4; j++) {
        const int e0 = eg * 8 + 2 * j;
        const float b_lo = bias[e0],     b_hi = bias[e0 + 1];
        const float v_lo = vbias[e0],    v_hi = vbias[e0 + 1];
#pragma unroll
        for (int i = 0; i < 4; i++) {
            F2U c; c.u = acc[i][j];
            float lo = c.f.x + b_lo + (mmask[i] ? v_lo : 0.0f);
            float hi = c.f.y + b_hi + (mmask[i] ? v_hi : 0.0f);
            Lg[tg * 4 + i][e0]     = lo;
            Lg[tg * 4 + i][e0 + 1] = hi;
        }
    }
    __syncthreads();

    // --- top-4 + softmax: one thread per token (64 active threads) ---
    if (tid < MT) {
        const int t = tid;
        float v0 = -INFINITY, v1 = -INFINITY, v2 = -INFINITY, v3 = -INFINITY;
        int   i0 = 0, i1 = 0, i2 = 0, i3 = 0;
#pragma unroll 8
        for (int e = 0; e < NE; e++) {
            float v = Lg[t][e];
            // strict '>' keeps earlier (smaller) index ahead on ties, matching jax top_k
            if (v > v2) {
                if (v > v0)      { v3 = v2; i3 = i2; v2 = v1; i2 = i1; v1 = v0; i1 = i0; v0 = v; i0 = e; }
                else if (v > v1) { v3 = v2; i3 = i2; v2 = v1; i2 = i1; v1 = v; i1 = e; }
                else             { v3 = v2; i3 = i2; v2 = v; i2 = e; }
            } else if (v > v3)   { v3 = v; i3 = e; }
        }
        // softmax over the 4 selected logits (max-subtracted, like jax.nn.softmax)
        float e1 = __expf(0.0f);  // keep ordering explicit; e1 of max term
        e1 = 1.0f;
        float x1 = expf(v1 - v0);
        float x2 = expf(v2 - v0);
        float x3 = expf(v3 - v0);
        float inv = 1.0f / (e1 + x1 + x2 + x3);
        float p0 = e1 * inv, p1 = x1 * inv, p2 = x2 * inv, p3 = x3 * inv;

        s_top_i[t][0] = i0; s_top_i[t][1] = i1; s_top_i[t][2] = i2; s_top_i[t][3] = i3;
        s_top_p[t][0] = p0; s_top_p[t][1] = p1; s_top_p[t][2] = p2; s_top_p[t][3] = p3;

        if (write_idx) {
            float* io = out + (size_t)T_TOKENS * NE + (size_t)(row0 + t) * TOPK;
            io[0] = (float)i0; io[1] = (float)i1; io[2] = (float)i2; io[3] = (float)i3;
        }
    }
    __syncthreads();

    // --- coalesced dense scatter: 64x128 tile, float4 per thread-iteration ---
    float4* out4 = (float4*)out;
    for (int q = tid; q < MT * NE / 4; q += THREADS) {
        const int t  = q >> 5;            // token within tile
        const int c4 = q & 31;            // float4 column
        const int e0 = c4 * 4;
        const int ti0 = s_top_i[t][0], ti1 = s_top_i[t][1], ti2 = s_top_i[t][2], ti3 = s_top_i[t][3];
        const float p0 = s_top_p[t][0], p1 = s_top_p[t][1], p2 = s_top_p[t][2], p3 = s_top_p[t][3];
        float4 o;
        float* of = (float*)&o;
#pragma unroll
        for (int j = 0; j < 4; j++) {
            const int e = e0 + j;
            float v = 0.0f;
            if (e == ti0) v = p0;
            else if (e == ti1) v = p1;
            else if (e == ti2) v = p2;
            else if (e == ti3) v = p3;
            of[j] = v;
        }
        out4[(size_t)(row0 + t) * (NE / 4) + c4] = o;
    }
}

extern "C" void kernel_launch(void* const* d_in, const int* in_sizes, int n_in,
                              void* d_out, int out_size)
{
    const float* X     = (const float*)d_in[0];   // (4,4096,2880) f32
    const int*   mask  = (const int*)  d_in[1];   // (4,4096) bool -> int32
    const float* W     = (const float*)d_in[2];   // (128,2880) f32
    const float* bias  = (const float*)d_in[3];   // (128,)
    const float* vbias = (const float*)d_in[4];   // (128,)
    float* out = (float*)d_out;

    // 1) transpose weight into __device__ scratch (tiny: 1.5 MB)
    transpose_w_kernel<<<(HID * NE + 255) / 256, 256>>>(W);

    // 2) fused GEMM + topk + softmax + scatter
    const int write_idx =
        (out_size >= T_TOKENS * NE + T_TOKENS * TOPK) ? 1 : 0;
    router_kernel<<<T_TOKENS / MT, THREADS>>>(X, mask, bias, vbias, out, write_idx);
}

// round 6
// speedup vs baseline: 1.9077x; 1.9077x over previous
#include <cuda_runtime.h>
#include <cuda_bf16.h>
#include <cstdint>
#include <math.h>

// Problem constants
#define T_TOKENS 16384
#define HID      2880
#define NE       128
#define TOPK     4

// Tiling
#define MT       64               // tokens per block
#define KB       16               // K-tile depth
#define THREADS  128              // 8 token-groups x 16 expert-groups, 8x8 thread tile
#define NTILES   (HID / KB)       // 180

// ---- packed f32x2 helpers (sm_103a; ptxas never emits these from C++) ----
#define FMA_F32X2(d, a, b, c) \
    asm("fma.rn.f32x2 %0, %1, %2, %3;" : "=l"(d) : "l"(a), "l"(b), "l"(c))
#define PACK_DUP_F32X2(out, f) do {                                    \
    unsigned int _ai = __float_as_uint(f);                             \
    asm("mov.b64 %0, {%1, %2};" : "=l"(out) : "r"(_ai), "r"(_ai));     \
} while (0)

// ---- cp.async helpers ----
#define CP_ASYNC16(dst_ptr, src_ptr) do {                                        \
    unsigned _d = (unsigned)__cvta_generic_to_shared(dst_ptr);                   \
    asm volatile("cp.async.cg.shared.global [%0], [%1], 16;" :: "r"(_d), "l"(src_ptr)); \
} while (0)
#define CP_COMMIT()  asm volatile("cp.async.commit_group;")
#define CP_WAIT0()   asm volatile("cp.async.wait_group 0;")

// Pre-transposed weight: g_Wt[k][e] = W[e][k]   (1.47 MB static scratch, L2-resident)
__device__ float g_Wt[HID * NE];

union F2U { unsigned long long u; float2 f; };

// Coalesced tiled transpose: W[e][k] -> g_Wt[k][e]
__global__ void transpose_w_kernel(const float* __restrict__ W) {
    __shared__ float tile[32][33];
    const int k0 = blockIdx.x * 32;
    const int e0 = blockIdx.y * 32;
    const int tx = threadIdx.x;
    const int ty = threadIdx.y;     // block (32, 8)
#pragma unroll
    for (int r = 0; r < 32; r += 8)
        tile[ty + r][tx] = W[(size_t)(e0 + ty + r) * HID + k0 + tx];
    __syncthreads();
#pragma unroll
    for (int r = 0; r < 32; r += 8)
        g_Wt[(size_t)(k0 + ty + r) * NE + e0 + tx] = tile[tx][ty + r];
}

__global__ __launch_bounds__(THREADS)
void router_kernel(const float* __restrict__ X,
                   const int*   __restrict__ mask,
                   const float* __restrict__ bias,
                   const float* __restrict__ vbias,
                   float* __restrict__ out,
                   int write_idx)
{
    // GEMM staging (double-buffered) aliased with the logits scratch:
    // GEMM phase finishes (barrier) before Lg is written.
    __shared__ union {
        struct {
            float As[2][KB][MT];     // 8 KB  (A transposed: [k][token])
            float Bs[2][KB][NE];     // 16 KB (Wt tile, natural [k][e])
        } t;
        float Lg[MT][NE + 1];        // 33 KB (pad 129 -> conflict-free column scan)
    } sm;
    __shared__ int   s_top_i[MT][TOPK];
    __shared__ float s_top_p[MT][TOPK];

    const int tid  = threadIdx.x;
    const int eg   = tid & 15;           // expert group
    const int tg   = tid >> 4;           // token group: tokens tg*8 .. tg*8+7
    const int row0 = blockIdx.x * MT;

    // 8 tokens x 8 experts per thread = 32 f32x2 accumulators.
    // Expert pairs (split layout for conflict-free stride-16B B reads):
    //   j=0: (eg*4, eg*4+1)   j=1: (eg*4+2, eg*4+3)
    //   j=2: (64+eg*4, ...)   j=3: (64+eg*4+2, ...)
    unsigned long long acc[8][4];
#pragma unroll
    for (int i = 0; i < 8; i++)
#pragma unroll
        for (int j = 0; j < 4; j++) acc[i][j] = 0ULL;

    // --- load mappings ---
    // A: 256 float4 per tile; thread -> token at=tid>>1, chunks ac, ac+1
    const int at = tid >> 1;
    const int ac = (tid & 1) * 2;
    const float* Xp = X + (size_t)(row0 + at) * HID + ac * 4;
    // B: 512 float4 per tile; 4 cp.async per thread: row bk + r*4, col4 be4
    const int bk  = tid >> 5;
    const int be4 = tid & 31;

    // ---- prologue: stage tile 0 ----
    {
        float4 a0 = *(const float4*)(Xp);
        float4 a1 = *(const float4*)(Xp + 4);
#pragma unroll
        for (int r = 0; r < 4; r++)
            CP_ASYNC16(&sm.t.Bs[0][bk + r * 4][be4 * 4],
                       g_Wt + (size_t)(bk + r * 4) * NE + be4 * 4);
        CP_COMMIT();
#pragma unroll
        for (int j = 0; j < 4; j++) {
            sm.t.As[0][ac * 4 + j][at]     = ((const float*)&a0)[j];
            sm.t.As[0][ac * 4 + 4 + j][at] = ((const float*)&a1)[j];
        }
        CP_WAIT0();
        __syncthreads();
    }

    // ---- main loop: one barrier per K-tile, prefetch hidden under compute ----
    for (int it = 0; it < NTILES; ++it) {
        const int cur = it & 1;
        const int nxt = cur ^ 1;
        const int ktn = (it + 1) * KB;
        float4 na0, na1;

        if (it + 1 < NTILES) {
            na0 = *(const float4*)(Xp + ktn);
            na1 = *(const float4*)(Xp + ktn + 4);
#pragma unroll
            for (int r = 0; r < 4; r++)
                CP_ASYNC16(&sm.t.Bs[nxt][bk + r * 4][be4 * 4],
                           g_Wt + (size_t)(ktn + bk + r * 4) * NE + be4 * 4);
            CP_COMMIT();
        }

#pragma unroll
        for (int kk = 0; kk < KB; kk++) {
            const float4 aA = *(const float4*)&sm.t.As[cur][kk][tg * 8];
            const float4 aB = *(const float4*)&sm.t.As[cur][kk][tg * 8 + 4];
            const ulonglong2 b0 = *(const ulonglong2*)&sm.t.Bs[cur][kk][eg * 4];
            const ulonglong2 b1 = *(const ulonglong2*)&sm.t.Bs[cur][kk][64 + eg * 4];
            const float av[8] = {aA.x, aA.y, aA.z, aA.w, aB.x, aB.y, aB.z, aB.w};
#pragma unroll
            for (int i = 0; i < 8; i++) {
                unsigned long long ad;
                PACK_DUP_F32X2(ad, av[i]);
                FMA_F32X2(acc[i][0], ad, b0.x, acc[i][0]);
                FMA_F32X2(acc[i][1], ad, b0.y, acc[i][1]);
                FMA_F32X2(acc[i][2], ad, b1.x, acc[i][2]);
                FMA_F32X2(acc[i][3], ad, b1.y, acc[i][3]);
            }
        }

        if (it + 1 < NTILES) {
#pragma unroll
            for (int j = 0; j < 4; j++) {
                sm.t.As[nxt][ac * 4 + j][at]     = ((const float*)&na0)[j];
                sm.t.As[nxt][ac * 4 + 4 + j][at] = ((const float*)&na1)[j];
            }
            CP_WAIT0();
        }
        __syncthreads();    // tile boundary (also fences the Lg aliasing below)
    }

    // --- epilogue: bias (+ vision bias), stage logits into aliased smem ---
    int mm[8];
#pragma unroll
    for (int i = 0; i < 8; i++) mm[i] = mask[row0 + tg * 8 + i];

    const int e0s[4] = {eg * 4, eg * 4 + 2, 64 + eg * 4, 64 + eg * 4 + 2};
#pragma unroll
    for (int j = 0; j < 4; j++) {
        const int e0 = e0s[j];
        const float b_lo = bias[e0],  b_hi = bias[e0 + 1];
        const float v_lo = vbias[e0], v_hi = vbias[e0 + 1];
#pragma unroll
        for (int i = 0; i < 8; i++) {
            F2U c; c.u = acc[i][j];
            sm.Lg[tg * 8 + i][e0]     = c.f.x + b_lo + (mm[i] ? v_lo : 0.0f);
            sm.Lg[tg * 8 + i][e0 + 1] = c.f.y + b_hi + (mm[i] ? v_hi : 0.0f);
        }
    }
    __syncthreads();

    // --- top-4 + softmax: one thread per token (64 of 128 active) ---
    if (tid < MT) {
        const int t = tid;
        float v0 = -INFINITY, v1 = -INFINITY, v2 = -INFINITY, v3 = -INFINITY;
        int   i0 = 0, i1 = 0, i2 = 0, i3 = 0;
#pragma unroll 8
        for (int e = 0; e < NE; e++) {
            float v = sm.Lg[t][e];
            // strict '>' keeps earlier index ahead on ties, matching jax top_k
            if (v > v2) {
                if (v > v0)      { v3 = v2; i3 = i2; v2 = v1; i2 = i1; v1 = v0; i1 = i0; v0 = v; i0 = e; }
                else if (v > v1) { v3 = v2; i3 = i2; v2 = v1; i2 = i1; v1 = v; i1 = e; }
                else             { v3 = v2; i3 = i2; v2 = v; i2 = e; }
            } else if (v > v3)   { v3 = v; i3 = e; }
        }
        const float x1 = expf(v1 - v0);
        const float x2 = expf(v2 - v0);
        const float x3 = expf(v3 - v0);
        const float inv = 1.0f / (1.0f + x1 + x2 + x3);

        s_top_i[t][0] = i0; s_top_i[t][1] = i1; s_top_i[t][2] = i2; s_top_i[t][3] = i3;
        s_top_p[t][0] = inv; s_top_p[t][1] = x1 * inv; s_top_p[t][2] = x2 * inv; s_top_p[t][3] = x3 * inv;

        if (write_idx) {
            float* io = out + (size_t)T_TOKENS * NE + (size_t)(row0 + t) * TOPK;
            io[0] = (float)i0; io[1] = (float)i1; io[2] = (float)i2; io[3] = (float)i3;
        }
    }
    __syncthreads();

    // --- coalesced dense scatter: 64x128 tile, float4 per thread-iteration ---
    float4* out4 = (float4*)out;
    for (int q = tid; q < MT * NE / 4; q += THREADS) {
        const int t  = q >> 5;
        const int c4 = q & 31;
        const int e0 = c4 * 4;
        const int ti0 = s_top_i[t][0], ti1 = s_top_i[t][1], ti2 = s_top_i[t][2], ti3 = s_top_i[t][3];
        const float p0 = s_top_p[t][0], p1 = s_top_p[t][1], p2 = s_top_p[t][2], p3 = s_top_p[t][3];
        float4 o;
        float* of = (float*)&o;
#pragma unroll
        for (int j = 0; j < 4; j++) {
            const int e = e0 + j;
            float v = 0.0f;
            if (e == ti0) v = p0;
            else if (e == ti1) v = p1;
            else if (e == ti2) v = p2;
            else if (e == ti3) v = p3;
            of[j] = v;
        }
        out4[(size_t)(row0 + t) * (NE / 4) + c4] = o;
    }
}

extern "C" void kernel_launch(void* const* d_in, const int* in_sizes, int n_in,
                              void* d_out, int out_size)
{
    const float* X     = (const float*)d_in[0];   // (4,4096,2880) f32
    const int*   mask  = (const int*)  d_in[1];   // (4,4096) bool -> int32
    const float* W     = (const float*)d_in[2];   // (128,2880) f32
    const float* bias  = (const float*)d_in[3];   // (128,)
    const float* vbias = (const float*)d_in[4];   // (128,)
    float* out = (float*)d_out;

    // 1) coalesced transpose of W into __device__ scratch (L2-resident 1.5 MB)
    transpose_w_kernel<<<dim3(HID / 32, NE / 32), dim3(32, 8)>>>(W);

    // 2) fused GEMM + topk + softmax + scatter
    const int write_idx =
        (out_size >= T_TOKENS * NE + T_TOKENS * TOPK) ? 1 : 0;
    router_kernel<<<T_TOKENS / MT, THREADS>>>(X, mask, bias, vbias, out, write_idx);
}